// round 4
// baseline (speedup 1.0000x reference)
#include <cuda_runtime.h>
#include <math.h>

#define BB 16
#define NN 8192
#define KK 128
#define MM (NN + KK)          // 8320
#define CH 34                 // 256-roi chunks (33 real + 1 empty pad)
#define FULLMASK 0xffffffffu

// scratch: bestk (bits 0..7) | fg flag (bit 8), per (b, m)
__device__ int g_combo[BB * MM];
__device__ int g_cnt[BB * CH];   // fg count per 256-chunk
__device__ int g_off[BB * CH];   // exclusive prefix of g_cnt per batch
__device__ int g_tot[BB];        // total fg per batch

// ---------------------------------------------------------------------------
// K1: IoU argmax. One block = (batch b, 512 rois). 256 threads, 2 rois each.
// Bit-faithful to the reference: iw = min(x2,gx2) - max(x1,gx1) + 1 (the +1
// applied AFTER the subtraction), areas from (x2-x1+1)*(y2-y1+1).
// ---------------------------------------------------------------------------
__global__ void __launch_bounds__(256)
ptl_iou_kernel(const float* __restrict__ rois_in,  // (B,N,5)
               const float* __restrict__ gt_in,    // (B,K,5)
               float4* __restrict__ out_inw,       // (B,M) float4
               float4* __restrict__ out_outw)      // (B,M) float4
{
    const int b   = blockIdx.y;
    const int c2  = blockIdx.x;        // 512-roi super-chunk, 0..16
    const int tid = threadIdx.x;
    const int lane = tid & 31;

    __shared__ float4 sbox[KK];        // raw {x1, y1, x2, y2}
    __shared__ float  sarea[KK];       // gt area (inf if zero-area)
    __shared__ float  sroi[512 * 5];
    __shared__ int    scnt[2];

    const float* gtb = gt_in + (size_t)b * KK * 5;
    for (int k = tid; k < KK; k += 256) {
        float x1 = gtb[k * 5 + 0];
        float y1 = gtb[k * 5 + 1];
        float x2 = gtb[k * 5 + 2];
        float y2 = gtb[k * 5 + 3];
        float gw = x2 - x1 + 1.0f;
        float gh = y2 - y1 + 1.0f;
        float a  = gw * gh;
        if (gw == 1.0f && gh == 1.0f) a = __int_as_float(0x7f800000);
        sbox[k]  = make_float4(x1, y1, x2, y2);
        sarea[k] = a;
    }

    const int mbase = c2 * 512;
    {   // stage this block's rois coalesced into shared
        int lim = (NN - mbase) * 5;
        if (lim > 512 * 5) lim = 512 * 5;
        if (lim < 0) lim = 0;
        const float* rb = rois_in + ((size_t)b * NN + mbase) * 5;
        for (int i = tid; i < lim; i += 256) sroi[i] = rb[i];
    }
    if (tid < 2) scnt[tid] = 0;
    __syncthreads();

    float rx1[2], ry1[2], rx2[2], ry2[2], rA[2];
    bool  valid[2], az[2];
#pragma unroll
    for (int j = 0; j < 2; j++) {
        const int m = mbase + j * 256 + tid;
        valid[j] = (m < MM);
        float x1, y1, x2, y2;
        if (m < NN) {
            const int li = (m - mbase) * 5;
            x1 = sroi[li + 1]; y1 = sroi[li + 2];
            x2 = sroi[li + 3]; y2 = sroi[li + 4];
        } else if (m < MM) {
            float4 g = sbox[m - NN];
            x1 = g.x; y1 = g.y; x2 = g.z; y2 = g.w;
        } else {
            x1 = 0.0f; y1 = 0.0f; x2 = 0.0f; y2 = 0.0f;
        }
        const float aw = x2 - x1 + 1.0f;
        const float ah = y2 - y1 + 1.0f;
        rx1[j] = x1; ry1[j] = y1; rx2[j] = x2; ry2[j] = y2;
        rA[j]  = aw * ah;
        az[j]  = (aw == 1.0f) && (ah == 1.0f);
    }

    float best[2] = { -1e30f, -1e30f };
    int   bk[2]   = { 0, 0 };

#pragma unroll 4
    for (int k = 0; k < KK; k++) {
        const float4 g  = sbox[k];
        const float  ga = sarea[k];
#pragma unroll
        for (int j = 0; j < 2; j++) {
            float iw = fminf(rx2[j], g.z) - fmaxf(rx1[j], g.x) + 1.0f;
            float ih = fminf(ry2[j], g.w) - fmaxf(ry1[j], g.y) + 1.0f;
            iw = fmaxf(iw, 0.0f);
            ih = fmaxf(ih, 0.0f);
            const float inter = iw * ih;
            const float ov = inter / (rA[j] + ga - inter);
            if (ov > best[j]) { best[j] = ov; bk[j] = k; }
        }
    }

#pragma unroll
    for (int j = 0; j < 2; j++) {
        const int m = mbase + j * 256 + tid;
        float bst = best[j];
        int   kk_ = bk[j];
        if (az[j]) { bst = -1.0f; kk_ = 0; }
        const bool fg = valid[j] && (bst >= 0.5f);

        if (valid[j]) {
            g_combo[b * MM + m] = kk_ | (fg ? 256 : 0);
            const float focal = fg ? (1.0f - bst) * (1.0f - bst) : 0.0f;
            const float ow    = (focal > 0.0f) ? 1.0f : 0.0f;
            out_inw [(size_t)b * MM + m] = make_float4(focal, focal, focal, focal);
            out_outw[(size_t)b * MM + m] = make_float4(ow, ow, ow, ow);
        }
        const unsigned bal = __ballot_sync(FULLMASK, fg);
        if (lane == 0) atomicAdd(&scnt[j], __popc(bal));
    }
    __syncthreads();
    if (tid < 2) g_cnt[b * CH + 2 * c2 + tid] = scnt[tid];
}

// ---------------------------------------------------------------------------
// K2: tiny scan. One block, one warp per batch; exclusive prefix over the
// 34 chunk counts + per-batch fg total.
// ---------------------------------------------------------------------------
__global__ void __launch_bounds__(512)
ptl_scan_kernel()
{
    const int warp = threadIdx.x >> 5;   // = batch
    const int lane = threadIdx.x & 31;
    if (warp >= BB) return;

    int v0 = g_cnt[warp * CH + lane];
    int v1 = (lane < CH - 32) ? g_cnt[warp * CH + 32 + lane] : 0;

    int s0 = v0;
#pragma unroll
    for (int off = 1; off < 32; off <<= 1) {
        int t = __shfl_up_sync(FULLMASK, s0, off);
        if (lane >= off) s0 += t;
    }
    const int tot32 = __shfl_sync(FULLMASK, s0, 31);

    int s1 = v1;
#pragma unroll
    for (int off = 1; off < 32; off <<= 1) {
        int t = __shfl_up_sync(FULLMASK, s1, off);
        if (lane >= off) s1 += t;
    }
    const int tot = tot32 + __shfl_sync(FULLMASK, s1, 31);

    g_off[warp * CH + lane] = s0 - v0;
    if (lane < CH - 32) g_off[warp * CH + 32 + lane] = tot32 + s1 - v1;
    if (lane == 0) g_tot[warp] = tot;
}

// ---------------------------------------------------------------------------
// K3: parallel scatter. One block = (batch b, 256-roi chunk c). Local ballot
// scan + precomputed chunk base -> stable fg/bg partition destination.
// ---------------------------------------------------------------------------
__global__ void __launch_bounds__(256)
ptl_scatter_kernel(const float* __restrict__ rois_in,  // (B,N,5)
                   const float* __restrict__ gt_in,    // (B,K,5)
                   float* __restrict__ out_rois,       // (B,M,5)
                   float* __restrict__ out_lab,        // (B,M)
                   float4* __restrict__ out_tgt)       // (B,M) float4
{
    const int b    = blockIdx.y;
    const int c    = blockIdx.x;     // 0..32
    const int tid  = threadIdx.x;
    const int lane = tid & 31;
    const int warp = tid >> 5;

    __shared__ float sgt[KK * 5];
    __shared__ float sroi[256 * 5];
    __shared__ int   swsum[8];

    const float* gtb = gt_in + (size_t)b * KK * 5;
    for (int i = tid; i < KK * 5; i += 256) sgt[i] = gtb[i];

    const int mbase = c * 256;
    {
        int lim = (NN - mbase) * 5;
        if (lim > 256 * 5) lim = 256 * 5;
        if (lim < 0) lim = 0;
        const float* rb = rois_in + ((size_t)b * NN + mbase) * 5;
        for (int i = tid; i < lim; i += 256) sroi[i] = rb[i];
    }

    const int m = mbase + tid;
    int combo = 0, flag = 0;
    if (m < MM) {
        combo = g_combo[b * MM + m];
        flag  = (combo >> 8) & 1;
    }

    const unsigned bal = __ballot_sync(FULLMASK, flag != 0);
    const int wpre = __popc(bal & ((1u << lane) - 1u));
    if (lane == 0) swsum[warp] = __popc(bal);
    __syncthreads();

    int wbase = 0;
#pragma unroll
    for (int w = 0; w < 8; w++)
        if (w < warp) wbase += swsum[w];

    const int prefix = g_off[b * CH + c] + wbase + wpre;  // #fg in [0, m)
    const int totfg  = g_tot[b];

    if (m < MM) {
        const int bestk = combo & 255;
        const int dest  = flag ? prefix : (totfg + (m - prefix));

        float x1, y1, x2, y2;
        if (m < NN) {
            const int li = tid * 5;
            x1 = sroi[li + 1]; y1 = sroi[li + 2];
            x2 = sroi[li + 3]; y2 = sroi[li + 4];
        } else {
            const float* g = &sgt[(m - NN) * 5];
            x1 = g[0]; y1 = g[1]; x2 = g[2]; y2 = g[3];
        }

        const size_t ro = ((size_t)b * MM + dest) * 5;
        out_rois[ro + 0] = (float)b;
        out_rois[ro + 1] = x1;
        out_rois[ro + 2] = y1;
        out_rois[ro + 3] = x2;
        out_rois[ro + 4] = y2;

        const float cls = sgt[bestk * 5 + 4];
        const float lab = flag ? cls : 0.0f;
        out_lab[(size_t)b * MM + dest] = lab;

        float t0 = 0.0f, t1 = 0.0f, t2 = 0.0f, t3 = 0.0f;
        if (lab > 0.0f) {
            const float gx1 = sgt[bestk * 5 + 0];
            const float gy1 = sgt[bestk * 5 + 1];
            const float gx2 = sgt[bestk * 5 + 2];
            const float gy2 = sgt[bestk * 5 + 3];
            const float ew  = x2 - x1 + 1.0f;
            const float eh  = y2 - y1 + 1.0f;
            const float ecx = x1 + 0.5f * ew;
            const float ecy = y1 + 0.5f * eh;
            const float gw  = gx2 - gx1 + 1.0f;
            const float gh  = gy2 - gy1 + 1.0f;
            const float gcx = gx1 + 0.5f * gw;
            const float gcy = gy1 + 0.5f * gh;
            t0 = ((gcx - ecx) / ew) / 0.1f;
            t1 = ((gcy - ecy) / eh) / 0.1f;
            t2 = logf(gw / ew) / 0.2f;
            t3 = logf(gh / eh) / 0.2f;
        }
        out_tgt[(size_t)b * MM + dest] = make_float4(t0, t1, t2, t3);
    }
}

// ---------------------------------------------------------------------------
extern "C" void kernel_launch(void* const* d_in, const int* in_sizes, int n_in,
                              void* d_out, int out_size)
{
    const float* rois = (const float*)d_in[0];   // (16, 8192, 5) f32
    const float* gt   = (const float*)d_in[1];   // (16, 128, 5) f32
    float* out = (float*)d_out;

    // outputs concatenated in reference tuple order
    float* out_rois = out;                                   // B*M*5
    float* out_lab  = out_rois + (size_t)BB * MM * 5;        // B*M
    float* out_tgt  = out_lab  + (size_t)BB * MM;            // B*M*4
    float* out_inw  = out_tgt  + (size_t)BB * MM * 4;        // B*M*4
    float* out_outw = out_inw  + (size_t)BB * MM * 4;        // B*M*4

    dim3 g1(17, BB);
    ptl_iou_kernel<<<g1, 256>>>(rois, gt, (float4*)out_inw, (float4*)out_outw);
    ptl_scan_kernel<<<1, 512>>>();
    dim3 g3(33, BB);
    ptl_scatter_kernel<<<g3, 256>>>(rois, gt, out_rois, out_lab,
                                    (float4*)out_tgt);
}